// round 7
// baseline (speedup 1.0000x reference)
#include <cuda_runtime.h>
#include <cuda_bf16.h>
#include <cstdint>

// Problem constants
#define BHN 64          // B*H
#define TT 1024         // sequence length
#define DD 128          // head dim
static __device__ __constant__ float INV_TEMP = 0.08838834764831845f;  // 1/sqrt(128)

// ---------------------------------------------------------------------------
// Pre-split bf16 scratch (hi/lo pairs).
// ---------------------------------------------------------------------------
__device__ __align__(16) unsigned char g_qh[(size_t)BHN * TT * DD * 2];  // [bh][t][d] (scaled)
__device__ __align__(16) unsigned char g_ql[(size_t)BHN * TT * DD * 2];
__device__ __align__(16) unsigned char g_kh[(size_t)BHN * TT * DD * 2];  // [bh][t][d]
__device__ __align__(16) unsigned char g_kl[(size_t)BHN * TT * DD * 2];
__device__ __align__(16) unsigned char g_vh[(size_t)BHN * DD * TT * 2];  // [bh][d][t]
__device__ __align__(16) unsigned char g_vl[(size_t)BHN * DD * TT * 2];
__device__ __align__(16) unsigned char g_fh[(size_t)BHN * DD * DD * 2];  // [bh][e][d]
__device__ __align__(16) unsigned char g_fl[(size_t)BHN * DD * DD * 2];

typedef unsigned long long u64t;

// ---------------------------------------------------------------------------
// helpers
// ---------------------------------------------------------------------------
__device__ __forceinline__ uint32_t smem_u32(const void* p) {
    uint32_t a;
    asm("{ .reg .u64 t; cvta.to.shared.u64 t, %1; cvt.u32.u64 %0, t; }" : "=r"(a) : "l"(p));
    return a;
}
__device__ __forceinline__ uint32_t pack_bf2(float lo, float hi) {
    uint32_t r;
    asm("cvt.rn.bf16x2.f32 %0, %1, %2;" : "=r"(r) : "f"(hi), "f"(lo));
    return r;
}
__device__ __forceinline__ void split2(float v0, float v1, uint32_t& hp, uint32_t& lp) {
    hp = pack_bf2(v0, v1);
    float h0 = __uint_as_float(hp << 16);
    float h1 = __uint_as_float(hp & 0xFFFF0000u);
    lp = pack_bf2(v0 - h0, v1 - h1);
}
__device__ __forceinline__ void ldsm4(uint32_t addr, uint32_t r[4]) {
    asm volatile("ldmatrix.sync.aligned.m8n8.x4.shared.b16 {%0,%1,%2,%3}, [%4];"
        : "=r"(r[0]), "=r"(r[1]), "=r"(r[2]), "=r"(r[3]) : "r"(addr));
}
__device__ __forceinline__ void mma16816(float c[4], const uint32_t a[4],
                                         uint32_t b0, uint32_t b1) {
    asm volatile("mma.sync.aligned.m16n8k16.row.col.f32.bf16.bf16.f32 "
        "{%0,%1,%2,%3}, {%4,%5,%6,%7}, {%8,%9}, {%0,%1,%2,%3};"
        : "+f"(c[0]), "+f"(c[1]), "+f"(c[2]), "+f"(c[3])
        : "r"(a[0]), "r"(a[1]), "r"(a[2]), "r"(a[3]), "r"(b0), "r"(b1));
}
__device__ __forceinline__ void cpasync16(uint32_t dst, const void* src) {
    asm volatile("cp.async.cg.shared.global [%0], [%1], 16;" :: "r"(dst), "l"(src));
}
#define CP_COMMIT() asm volatile("cp.async.commit_group;" ::: "memory")
#define CP_WAIT1()  asm volatile("cp.async.wait_group 1;" ::: "memory")
#define CP_WAIT0()  asm volatile("cp.async.wait_group 0;" ::: "memory")

// TILE128: row stride 256B (128 halves), 16x16B chunks, ch ^= row&7 (R5-verified)
// TILE64 : row stride 128B (64 halves),  8x16B chunks, ch ^= row&7 (R6-verified)
__device__ __forceinline__ uint32_t a128(uint32_t base, int fr, int ksi,
                                         int rA, int xr, int kq) {
    return base + (uint32_t)((fr + rA) * 256 + (((ksi * 2 + kq) ^ xr) << 4));
}
__device__ __forceinline__ uint32_t a64(uint32_t base, int fr, int ksi,
                                        int rA, int xr, int kq) {
    return base + (uint32_t)((fr + rA) * 128 + (((ksi * 2 + kq) ^ xr) << 4));
}
__device__ __forceinline__ uint32_t SWZ128(int row, int k) {
    return (uint32_t)(row * 256 + ((((k >> 3) ^ (row & 7)) << 4)) + ((k & 7) << 1));
}
__device__ __forceinline__ uint32_t SWZ64(int row, int k) {
    return (uint32_t)(row * 128 + ((((k >> 3) ^ (row & 7)) << 4)) + ((k & 7) << 1));
}

// loaders (512-thread blocks)
__device__ __forceinline__ void ld_t128_r128(uint32_t dst, const unsigned char* src,
                                             int stride, int tid) {
    #pragma unroll
    for (int i = 0; i < 4; i++) {
        int idx = i * 512 + tid;
        int row = idx >> 4, ch = idx & 15;
        cpasync16(dst + row * 256 + (((ch ^ (row & 7)) & 15) << 4),
                  src + (size_t)row * stride + ch * 16);
    }
}
__device__ __forceinline__ void ld_t128_r64(uint32_t dst, const unsigned char* src,
                                            int stride, int tid) {
    #pragma unroll
    for (int i = 0; i < 2; i++) {
        int idx = i * 512 + tid;
        int row = idx >> 4, ch = idx & 15;
        cpasync16(dst + row * 256 + (((ch ^ (row & 7)) & 15) << 4),
                  src + (size_t)row * stride + ch * 16);
    }
}
__device__ __forceinline__ void ld_t64_r128(uint32_t dst, const unsigned char* src,
                                            int stride, int tid) {
    #pragma unroll
    for (int i = 0; i < 2; i++) {
        int idx = i * 512 + tid;
        int row = idx >> 3, ch = idx & 7;
        cpasync16(dst + row * 128 + ((ch ^ (row & 7)) << 4),
                  src + (size_t)row * stride + ch * 16);
    }
}

// ---------------------------------------------------------------------------
// Prep kernels
// ---------------------------------------------------------------------------
__global__ void qk_split_kernel(const float* __restrict__ q, const float* __restrict__ k) {
    const bool isq = (blockIdx.y == 0);
    const float* src = isq ? q : k;
    unsigned char* hi = isq ? g_qh : g_kh;
    unsigned char* lo = isq ? g_ql : g_kl;
    const float scale = isq ? INV_TEMP : 1.0f;
    size_t i4 = (size_t)blockIdx.x * 256 + threadIdx.x;
    float4 v = ((const float4*)src)[i4];
    v.x *= scale; v.y *= scale; v.z *= scale; v.w *= scale;
    uint32_t hp0, lp0, hp1, lp1;
    split2(v.x, v.y, hp0, lp0);
    split2(v.z, v.w, hp1, lp1);
    ((uint2*)hi)[i4] = make_uint2(hp0, hp1);
    ((uint2*)lo)[i4] = make_uint2(lp0, lp1);
}

__global__ void v_split_T_kernel(const float* __restrict__ v) {
    __shared__ float tile[32][33];
    const int t0 = blockIdx.x * 32;
    const int bh = blockIdx.y;
    const float* src = v + (size_t)bh * TT * DD;
    unsigned char* dh = g_vh + (size_t)bh * DD * TT * 2;
    unsigned char* dl = g_vl + (size_t)bh * DD * TT * 2;
    const int tid = threadIdx.x;
    for (int d0 = 0; d0 < DD; d0 += 32) {
        #pragma unroll
        for (int i = 0; i < 4; i++) {
            int idx = i * 256 + tid;
            int r = idx >> 5, c = idx & 31;
            tile[r][c] = src[(size_t)(t0 + r) * DD + d0 + c];
        }
        __syncthreads();
        #pragma unroll
        for (int i = 0; i < 2; i++) {
            int idx = i * 256 + tid;
            int r = idx >> 4, c2 = (idx & 15) * 2;
            float v0 = tile[c2][r], v1 = tile[c2 + 1][r];
            uint32_t hp, lp;
            split2(v0, v1, hp, lp);
            size_t off = ((size_t)(d0 + r) * TT + t0 + c2) * 2;
            *(uint32_t*)(dh + off) = hp;
            *(uint32_t*)(dl + off) = lp;
        }
        __syncthreads();
    }
}

__global__ void ft_split_T_kernel(const float* __restrict__ af) {
    __shared__ float tile[32][33];
    const int e0 = blockIdx.x * 32;
    const int bh = blockIdx.y;
    const float* src = af + (size_t)bh * DD * DD;
    unsigned char* dh = g_fh + (size_t)bh * DD * DD * 2;
    unsigned char* dl = g_fl + (size_t)bh * DD * DD * 2;
    const int tid = threadIdx.x;
    for (int d0 = 0; d0 < DD; d0 += 32) {
        #pragma unroll
        for (int i = 0; i < 4; i++) {
            int idx = i * 256 + tid;
            int r = idx >> 5, c = idx & 31;
            tile[r][c] = src[(size_t)(d0 + r) * DD + e0 + c];
        }
        __syncthreads();
        #pragma unroll
        for (int i = 0; i < 2; i++) {
            int idx = i * 256 + tid;
            int r = idx >> 4, c2 = (idx & 15) * 2;
            float v0 = tile[c2][r], v1 = tile[c2 + 1][r];
            uint32_t hp, lp;
            split2(v0, v1, hp, lp);
            size_t off = ((size_t)(e0 + r) * DD + d0 + c2) * 2;
            *(uint32_t*)(dh + off) = hp;
            *(uint32_t*)(dl + off) = lp;
        }
        __syncthreads();
    }
}

// ---------------------------------------------------------------------------
// Feature attention (CUDA-core f32x2; not the bottleneck)
// ---------------------------------------------------------------------------
__device__ __forceinline__ u64t pk2(float lo, float hi) {
    u64t r; asm("mov.b64 %0, {%1, %2};" : "=l"(r) : "f"(lo), "f"(hi)); return r;
}
__device__ __forceinline__ void fma2(u64t& d, u64t a, u64t b) {
    asm("fma.rn.f32x2 %0, %1, %2, %0;" : "+l"(d) : "l"(a), "l"(b));
}
__device__ __forceinline__ void up2(u64t v, float& a, float& b) {
    asm("mov.b64 {%0, %1}, %2;" : "=f"(a), "=f"(b) : "l"(v));
}

__global__ void __launch_bounds__(256) feature_attn_kernel(
    const float* __restrict__ qf, const float* __restrict__ kf,
    float* __restrict__ attn_f) {
    __shared__ float qs[32 * 34];
    __shared__ float ks[32 * 132];
    __shared__ float Sf[32 * 132];

    const int bh = blockIdx.y;
    const int d0blk = blockIdx.x * 32;
    const float* q = qf + (size_t)bh * TT * DD;
    const float* k = kf + (size_t)bh * TT * DD;
    const int tid = threadIdx.x;
    const int ty = tid >> 4, tx = tid & 15;
    const int r0 = ty * 2;
    const int e0 = tx * 8;

    u64t acc[2][4];
    #pragma unroll
    for (int i = 0; i < 2; i++)
        #pragma unroll
        for (int j = 0; j < 4; j++) acc[i][j] = 0ull;

    for (int tt = 0; tt < TT; tt += 32) {
        #pragma unroll
        for (int i = 0; i < 4; i++) {
            int idx = i * 256 + tid;
            int r = idx >> 5, c = idx & 31;
            qs[r * 34 + c] = q[(size_t)(tt + r) * DD + d0blk + c] * INV_TEMP;
        }
        #pragma unroll
        for (int i = 0; i < 4; i++) {
            int idx = i * 256 + tid;
            int r = idx >> 5, c4 = (idx & 31) * 4;
            *(float4*)&ks[r * 132 + c4] = *(const float4*)&k[(size_t)(tt + r) * DD + c4];
        }
        __syncthreads();
        #pragma unroll 4
        for (int t = 0; t < 32; t++) {
            float2 a = *(float2*)&qs[t * 34 + r0];
            ulonglong2 b0 = *(ulonglong2*)&ks[t * 132 + e0];
            ulonglong2 b1 = *(ulonglong2*)&ks[t * 132 + e0 + 4];
            u64t a0 = pk2(a.x, a.x), a1 = pk2(a.y, a.y);
            fma2(acc[0][0], a0, b0.x); fma2(acc[0][1], a0, b0.y);
            fma2(acc[0][2], a0, b1.x); fma2(acc[0][3], a0, b1.y);
            fma2(acc[1][0], a1, b0.x); fma2(acc[1][1], a1, b0.y);
            fma2(acc[1][2], a1, b1.x); fma2(acc[1][3], a1, b1.y);
        }
        __syncthreads();
    }

    #pragma unroll
    for (int i = 0; i < 2; i++) {
        float x[8];
        up2(acc[i][0], x[0], x[1]); up2(acc[i][1], x[2], x[3]);
        up2(acc[i][2], x[4], x[5]); up2(acc[i][3], x[6], x[7]);
        *(float4*)&Sf[(r0 + i) * 132 + e0]     = make_float4(x[0], x[1], x[2], x[3]);
        *(float4*)&Sf[(r0 + i) * 132 + e0 + 4] = make_float4(x[4], x[5], x[6], x[7]);
    }
    __syncthreads();

    const int lane = tid & 31, w = tid >> 5;
    float* af = attn_f + (size_t)bh * DD * DD;
    #pragma unroll
    for (int rr = 0; rr < 4; rr++) {
        int r = w * 4 + rr;
        float vv[4], mx = -1e30f;
        #pragma unroll
        for (int kk = 0; kk < 4; kk++) {
            vv[kk] = Sf[r * 132 + lane + 32 * kk];
            mx = fmaxf(mx, vv[kk]);
        }
        #pragma unroll
        for (int o = 16; o; o >>= 1) mx = fmaxf(mx, __shfl_xor_sync(~0u, mx, o));
        float ssum = 0.f;
        #pragma unroll
        for (int kk = 0; kk < 4; kk++) { vv[kk] = __expf(vv[kk] - mx); ssum += vv[kk]; }
        #pragma unroll
        for (int o = 16; o; o >>= 1) ssum += __shfl_xor_sync(~0u, ssum, o);
        float iv = 1.0f / ssum;
        #pragma unroll
        for (int kk = 0; kk < 4; kk++)
            af[(size_t)(d0blk + r) * DD + lane + 32 * kk] = vv[kk] * iv;
    }
}

// ---------------------------------------------------------------------------
// Fused time kernel (recompute design):
//   pass A: rowsums of exp(scores) — K chunks of 64, no HBM writes
//   pass B: recompute scores, write normalized attn_time once, MMA2 tv+=E@V
//   tail:   out = (tv @ F^T) * inv
// grid (8, 64), block 512.
// smem: Q(64K) | K(32K) | V(32K) | E(32K) | red/inv
// ---------------------------------------------------------------------------
#define SM_Q 0
#define SM_K 65536
#define SM_V 98304
#define SM_E 131072
#define SM_RED 163840
#define SM_INV 164352
#define F_SMEM 164864

__global__ void __launch_bounds__(512, 1) fused_time_kernel(
    float* __restrict__ out, float* __restrict__ attn_t) {
    extern __shared__ char sm[];
    const uint32_t sb = smem_u32(sm);
    float* red  = (float*)(sm + SM_RED);
    float* invs = (float*)(sm + SM_INV);

    const int bh = blockIdx.y;
    const int r0 = blockIdx.x * 128;
    const int tid = threadIdx.x;
    const int wid = tid >> 5, lane = tid & 31;
    const int g = lane >> 2, tig = lane & 3;
    const int rA = (lane & 7) + ((lane >> 3) & 1) * 8;
    const int xr = rA & 7, kq = lane >> 4;
    // pass A/B MMA1 mapping (128x64 tile): 32x16 warp tiles
    const int s_wm = wid & 3, s_wn = wid >> 2;
    // MMA2 / GEMM3 mapping (128x128 tile): 64x16 warp tiles
    const int t_wm = wid & 1, t_wn = wid >> 1;

    if (tid < 128) red[tid] = 0.f;

    const unsigned char* qh = g_qh + ((size_t)bh * TT + r0) * 256;
    const unsigned char* ql = g_ql + ((size_t)bh * TT + r0) * 256;
    const unsigned char* kh = g_kh + (size_t)bh * TT * 256;
    const unsigned char* kl = g_kl + (size_t)bh * TT * 256;
    const unsigned char* vh = g_vh + (size_t)bh * DD * 2048;
    const unsigned char* vl = g_vl + (size_t)bh * DD * 2048;

    // Q resident (group 0-ish; folded into first waits)
    ld_t128_r128(sb + SM_Q,         qh, 256, tid);
    ld_t128_r128(sb + SM_Q + 32768, ql, 256, tid);
    // pass A prologue: K[0] -> Kbuf, K[1] -> Vbuf
    ld_t128_r64(sb + SM_K,         kh, 256, tid);
    ld_t128_r64(sb + SM_K + 16384, kl, 256, tid);
    CP_COMMIT();                                     // group: Q + K0
    ld_t128_r64(sb + SM_V,         kh + 64 * 256, 256, tid);
    ld_t128_r64(sb + SM_V + 16384, kl + 64 * 256, 256, tid);
    CP_COMMIT();                                     // group: K1

    float rsum[4] = {0, 0, 0, 0};

    // ================= pass A =================
    for (int c = 0; c < 16; c++) {
        CP_WAIT1();                 // K[c] ready
        __syncthreads();
        const uint32_t kb = (c & 1) ? (sb + SM_V) : (sb + SM_K);

        float acc[2][2][4];
        #pragma unroll
        for (int mi = 0; mi < 2; mi++)
            #pragma unroll
            for (int nf = 0; nf < 2; nf++)
                #pragma unroll
                for (int j = 0; j < 4; j++) acc[mi][nf][j] = 0.f;

        #pragma unroll
        for (int ksi = 0; ksi < 8; ksi++) {
            uint32_t ah[2][4], al[2][4], bhv[4], blv[4];
            #pragma unroll
            for (int mi = 0; mi < 2; mi++) {
                int fr = s_wm * 32 + mi * 16;
                ldsm4(a128(sb + SM_Q, fr, ksi, rA, xr, kq), ah[mi]);
                ldsm4(a128(sb + SM_Q + 32768, fr, ksi, rA, xr, kq), al[mi]);
            }
            ldsm4(a128(kb, s_wn * 16, ksi, rA, xr, kq), bhv);
            ldsm4(a128(kb + 16384, s_wn * 16, ksi, rA, xr, kq), blv);
            #pragma unroll
            for (int mi = 0; mi < 2; mi++) {
                mma16816(acc[mi][0], ah[mi], bhv[0], bhv[2]);
                mma16816(acc[mi][1], ah[mi], bhv[1], bhv[3]);
                mma16816(acc[mi][0], ah[mi], blv[0], blv[2]);
                mma16816(acc[mi][1], ah[mi], blv[1], blv[3]);
                mma16816(acc[mi][0], al[mi], bhv[0], bhv[2]);
                mma16816(acc[mi][1], al[mi], bhv[1], bhv[3]);
            }
        }
        __syncthreads();            // all warps done reading K[c]
        if (c < 14) {               // prefetch K[c+2] into buf(c&1)
            const unsigned char* kh2 = kh + (size_t)(c + 2) * 64 * 256;
            const unsigned char* kl2 = kl + (size_t)(c + 2) * 64 * 256;
            uint32_t dst = (c & 1) ? (sb + SM_V) : (sb + SM_K);
            ld_t128_r64(dst,         kh2, 256, tid);
            ld_t128_r64(dst + 16384, kl2, 256, tid);
        }
        CP_COMMIT();
        // exp + rowsum (regs only)
        #pragma unroll
        for (int mi = 0; mi < 2; mi++)
            #pragma unroll
            for (int nf = 0; nf < 2; nf++) {
                rsum[mi * 2 + 0] += __expf(acc[mi][nf][0]) + __expf(acc[mi][nf][1]);
                rsum[mi * 2 + 1] += __expf(acc[mi][nf][2]) + __expf(acc[mi][nf][3]);
            }
    }

    // reduce rowsums -> invs
    #pragma unroll
    for (int j = 0; j < 4; j++) {
        rsum[j] += __shfl_xor_sync(~0u, rsum[j], 1);
        rsum[j] += __shfl_xor_sync(~0u, rsum[j], 2);
    }
    if (tig == 0) {
        #pragma unroll
        for (int mi = 0; mi < 2; mi++) {
            int row = s_wm * 32 + mi * 16 + g;
            atomicAdd(&red[row],     rsum[mi * 2 + 0]);
            atomicAdd(&red[row + 8], rsum[mi * 2 + 1]);
        }
    }
    CP_WAIT0();
    __syncthreads();
    if (tid < 128) invs[tid] = 1.0f / red[tid];
    __syncthreads();

    // ================= pass B =================
    // prologue: K[0], V[0]
    ld_t128_r64(sb + SM_K,         kh, 256, tid);
    ld_t128_r64(sb + SM_K + 16384, kl, 256, tid);
    CP_COMMIT();
    ld_t64_r128(sb + SM_V,         vh, 2048, tid);
    ld_t64_r128(sb + SM_V + 16384, vl, 2048, tid);
    CP_COMMIT();
    CP_WAIT1();                     // K[0] ready
    __syncthreads();

    float acc2[4][2][4];
    #pragma unroll
    for (int mi = 0; mi < 4; mi++)
        #pragma unroll
        for (int nf = 0; nf < 2; nf++)
            #pragma unroll
            for (int j = 0; j < 4; j++) acc2[mi][nf][j] = 0.f;

    float* at = attn_t + ((size_t)bh * TT + r0) * TT;

    for (int c = 0; c < 16; c++) {
        // ---- MMA1: scores chunk (uses Q, K[c]) ----
        float acc[2][2][4];
        #pragma unroll
        for (int mi = 0; mi < 2; mi++)
            #pragma unroll
            for (int nf = 0; nf < 2; nf++)
                #pragma unroll
                for (int j = 0; j < 4; j++) acc[mi][nf][j] = 0.f;

        #pragma unroll
        for (int ksi = 0; ksi < 8; ksi++) {
            uint32_t ah[2][4], al[2][4], bhv[4], blv[4];
            #pragma unroll
            for (int mi = 0; mi < 2; mi++) {
                int fr = s_wm * 32 + mi * 16;
                ldsm4(a128(sb + SM_Q, fr, ksi, rA, xr, kq), ah[mi]);
                ldsm4(a128(sb + SM_Q + 32768, fr, ksi, rA, xr, kq), al[mi]);
            }
            ldsm4(a128(sb + SM_K, s_wn * 16, ksi, rA, xr, kq), bhv);
            ldsm4(a128(sb + SM_K + 16384, s_wn * 16, ksi, rA, xr, kq), blv);
            #pragma unroll
            for (int mi = 0; mi < 2; mi++) {
                mma16816(acc[mi][0], ah[mi], bhv[0], bhv[2]);
                mma16816(acc[mi][1], ah[mi], bhv[1], bhv[3]);
                mma16816(acc[mi][0], ah[mi], blv[0], blv[2]);
                mma16816(acc[mi][1], ah[mi], blv[1], blv[3]);
                mma16816(acc[mi][0], al[mi], bhv[0], bhv[2]);
                mma16816(acc[mi][1], al[mi], bhv[1], bhv[3]);
            }
        }
        __syncthreads();            // K[c] fully read
        if (c < 15) {               // prefetch K[c+1]
            const unsigned char* kh1 = kh + (size_t)(c + 1) * 64 * 256;
            const unsigned char* kl1 = kl + (size_t)(c + 1) * 64 * 256;
            ld_t128_r64(sb + SM_K,         kh1, 256, tid);
            ld_t128_r64(sb + SM_K + 16384, kl1, 256, tid);
        }
        CP_COMMIT();

        // ---- epilogue: exp -> attn_t (normalized) + stage E in smem ----
        #pragma unroll
        for (int mi = 0; mi < 2; mi++) {
            int row = s_wm * 32 + mi * 16 + g;
            float iva = invs[row], ivb = invs[row + 8];
            #pragma unroll
            for (int nf = 0; nf < 2; nf++) {
                int col = s_wn * 16 + nf * 8 + tig * 2;
                float e0 = __expf(acc[mi][nf][0]);
                float e1 = __expf(acc[mi][nf][1]);
                float e2 = __expf(acc[mi][nf][2]);
                float e3 = __expf(acc[mi][nf][3]);
                *(float2*)&at[(size_t)row * TT + c * 64 + col] =
                    make_float2(e0 * iva, e1 * iva);
                *(float2*)&at[(size_t)(row + 8) * TT + c * 64 + col] =
                    make_float2(e2 * ivb, e3 * ivb);
                uint32_t hp, lp;
                split2(e0, e1, hp, lp);
                *(uint32_t*)(sm + SM_E + SWZ64(row, col)) = hp;
                *(uint32_t*)(sm + SM_E + 16384 + SWZ64(row, col)) = lp;
                split2(e2, e3, hp, lp);
                *(uint32_t*)(sm + SM_E + SWZ64(row + 8, col)) = hp;
                *(uint32_t*)(sm + SM_E + 16384 + SWZ64(row + 8, col)) = lp;
            }
        }
        CP_WAIT1();                 // V[c] ready (K[c+1] still in flight)
        __syncthreads();            // E visible

        // ---- MMA2: tv += E @ V[c] ----
        #pragma unroll
        for (int ksi = 0; ksi < 4; ksi++) {
            uint32_t ah[4][4], al[4][4], bhv[4], blv[4];
            #pragma unroll
            for (int mi = 0; mi < 4; mi++) {
                int fr = t_wm * 64 + mi * 16;
                ldsm4(a64(sb + SM_E, fr, ksi, rA, xr, kq), ah[mi]);
                ldsm4(a64(sb + SM_E + 16384, fr, ksi, rA, xr, kq), al[mi]);
            }
            ldsm4(a64(sb + SM_V, t_wn * 16, ksi, rA, xr, kq), bhv);
            ldsm4(a64(sb + SM_V + 16384, t_wn * 16, ksi, rA, xr, kq), blv);
            #pragma unroll
            for (int mi = 0; mi < 4; mi++) {
                mma16816(acc2[mi][0], ah[mi], bhv[0], bhv[2]);
                mma16816(acc2[mi][1], ah[mi], bhv[1], bhv[3]);
                mma16816(acc2[mi][0], ah[mi], blv[0], blv[2]);
                mma16816(acc2[mi][1], ah[mi], blv[1], blv[3]);
                mma16816(acc2[mi][0], al[mi], bhv[0], bhv[2]);
                mma16816(acc2[mi][1], al[mi], bhv[1], bhv[3]);
            }
        }
        __syncthreads();            // V[c], E fully read
        if (c < 15) {               // prefetch V[c+1]
            ld_t64_r128(sb + SM_V,         vh + (c + 1) * 128, 2048, tid);
            ld_t64_r128(sb + SM_V + 16384, vl + (c + 1) * 128, 2048, tid);
        }
        CP_COMMIT();
        CP_WAIT1();                 // K[c+1] ready
        __syncthreads();
    }

    // ================= GEMM3: out = (tv @ F^T) * inv =================
    // F^T rows 0-63 -> K region, rows 64-127 -> V region (hi + lo each)
    {
        const unsigned char* fhb = g_fh + (size_t)bh * DD * 256;
        const unsigned char* flb = g_fl + (size_t)bh * DD * 256;
        ld_t128_r64(sb + SM_K,         fhb, 256, tid);
        ld_t128_r64(sb + SM_K + 16384, flb, 256, tid);
        ld_t128_r64(sb + SM_V,         fhb + 64 * 256, 256, tid);
        ld_t128_r64(sb + SM_V + 16384, flb + 64 * 256, 256, tid);
        CP_COMMIT();
    }
    // stage tv split into Q region (TILE128 hi at +0, lo at +32768)
    #pragma unroll
    for (int mi = 0; mi < 4; mi++) {
        int row = t_wm * 64 + mi * 16 + g;
        #pragma unroll
        for (int nf = 0; nf < 2; nf++) {
            int d0v = t_wn * 16 + nf * 8 + tig * 2;
            uint32_t hp, lp;
            split2(acc2[mi][nf][0], acc2[mi][nf][1], hp, lp);
            *(uint32_t*)(sm + SM_Q + SWZ128(row, d0v)) = hp;
            *(uint32_t*)(sm + SM_Q + 32768 + SWZ128(row, d0v)) = lp;
            split2(acc2[mi][nf][2], acc2[mi][nf][3], hp, lp);
            *(uint32_t*)(sm + SM_Q + SWZ128(row + 8, d0v)) = hp;
            *(uint32_t*)(sm + SM_Q + 32768 + SWZ128(row + 8, d0v)) = lp;
        }
    }
    CP_WAIT0();
    __syncthreads();

    float acc3[4][2][4];
    #pragma unroll
    for (int mi = 0; mi < 4; mi++)
        #pragma unroll
        for (int nf = 0; nf < 2; nf++)
            #pragma unroll
            for (int j = 0; j < 4; j++) acc3[mi][nf][j] = 0.f;

    const uint32_t fb = (t_wn < 4) ? (sb + SM_K) : (sb + SM_V);
    const int nr3 = (t_wn & 3) * 16;
    #pragma unroll
    for (int ksi = 0; ksi < 8; ksi++) {
        uint32_t ah[4][4], al[4][4], bhv[4], blv[4];
        #pragma unroll
        for (int mi = 0; mi < 4; mi++) {
            int fr = t_wm * 64 + mi * 16;
            ldsm4(a128(sb + SM_Q, fr, ksi, rA, xr, kq), ah[mi]);
            ldsm4(a128(sb + SM_Q + 32768, fr, ksi, rA, xr, kq), al[mi]);
        }
        ldsm4(a128(fb, nr3, ksi, rA, xr, kq), bhv);
        ldsm4(a128(fb + 16384, nr3, ksi, rA, xr, kq), blv);
        #pragma unroll
        for (int mi = 0; mi < 4; mi++) {
            mma16816(acc3[mi][0], ah[mi], bhv[0], bhv[2]);
            mma16816(acc3[mi][1], ah[mi], bhv[1], bhv[3]);
            mma16816(acc3[mi][0], ah[mi], blv[0], blv[2]);
            mma16816(acc3[mi][1], ah[mi], blv[1], blv[3]);
            mma16816(acc3[mi][0], al[mi], bhv[0], bhv[2]);
            mma16816(acc3[mi][1], al[mi], bhv[1], bhv[3]);
        }
    }

    float* op = out + ((size_t)bh * TT + r0) * DD;
    #pragma unroll
    for (int mi = 0; mi < 4; mi++) {
        int row = t_wm * 64 + mi * 16 + g;
        float iva = invs[row], ivb = invs[row + 8];
        #pragma unroll
        for (int nf = 0; nf < 2; nf++) {
            int e = t_wn * 16 + nf * 8 + tig * 2;
            *(float2*)&op[(size_t)row * DD + e] =
                make_float2(acc3[mi][nf][0] * iva, acc3[mi][nf][1] * iva);
            *(float2*)&op[(size_t)(row + 8) * DD + e] =
                make_float2(acc3[mi][nf][2] * ivb, acc3[mi][nf][3] * ivb);
        }
    }
}

// ---------------------------------------------------------------------------
// Launch
// ---------------------------------------------------------------------------
extern "C" void kernel_launch(void* const* d_in, const int* in_sizes, int n_in,
                              void* d_out, int out_size) {
    const float* q_time    = (const float*)d_in[0];
    const float* k_time    = (const float*)d_in[1];
    const float* q_feature = (const float*)d_in[2];
    const float* k_feature = (const float*)d_in[3];
    const float* v         = (const float*)d_in[4];

    float* out    = (float*)d_out;                       // [BH][T][D]
    float* attn_t = out + (size_t)BHN * TT * DD;         // [BH][T][T]
    float* attn_f = attn_t + (size_t)BHN * TT * TT;      // [BH][D][D]

    cudaFuncSetAttribute(fused_time_kernel,
                         cudaFuncAttributeMaxDynamicSharedMemorySize, F_SMEM);

    qk_split_kernel<<<dim3(8192, 2), 256>>>(q_time, k_time);
    v_split_T_kernel<<<dim3(32, BHN), 256>>>(v);
    feature_attn_kernel<<<dim3(4, BHN), 256>>>(q_feature, k_feature, attn_f);
    ft_split_T_kernel<<<dim3(4, BHN), 256>>>(attn_f);
    fused_time_kernel<<<dim3(8, BHN), 512, F_SMEM>>>(out, attn_t);
}

// round 8
// speedup vs baseline: 1.1028x; 1.1028x over previous
#include <cuda_runtime.h>
#include <cuda_bf16.h>
#include <cstdint>

// Problem constants
#define BHN 64          // B*H
#define TT 1024         // sequence length
#define DD 128          // head dim
static __device__ __constant__ float INV_TEMP = 0.08838834764831845f;  // 1/sqrt(128)

// ---------------------------------------------------------------------------
// Pre-split bf16 scratch (hi/lo pairs).
// ---------------------------------------------------------------------------
__device__ __align__(16) unsigned char g_qh[(size_t)BHN * TT * DD * 2];  // [bh][t][d] (scaled)
__device__ __align__(16) unsigned char g_ql[(size_t)BHN * TT * DD * 2];
__device__ __align__(16) unsigned char g_kh[(size_t)BHN * TT * DD * 2];  // [bh][t][d]
__device__ __align__(16) unsigned char g_kl[(size_t)BHN * TT * DD * 2];
__device__ __align__(16) unsigned char g_vh[(size_t)BHN * DD * TT * 2];  // [bh][d][t]
__device__ __align__(16) unsigned char g_vl[(size_t)BHN * DD * TT * 2];
__device__ __align__(16) unsigned char g_fh[(size_t)BHN * DD * DD * 2];  // [bh][e][d]
__device__ __align__(16) unsigned char g_fl[(size_t)BHN * DD * DD * 2];
__device__ __align__(16) unsigned char g_eh[(size_t)BHN * TT * TT * 2];  // [bh][t][s] unnorm exp
__device__ __align__(16) unsigned char g_el[(size_t)BHN * TT * TT * 2];
__device__ float g_inv[BHN * TT];

typedef unsigned long long u64t;

// ---------------------------------------------------------------------------
// helpers
// ---------------------------------------------------------------------------
__device__ __forceinline__ uint32_t smem_u32(const void* p) {
    uint32_t a;
    asm("{ .reg .u64 t; cvta.to.shared.u64 t, %1; cvt.u32.u64 %0, t; }" : "=r"(a) : "l"(p));
    return a;
}
__device__ __forceinline__ uint32_t pack_bf2(float lo, float hi) {
    uint32_t r;
    asm("cvt.rn.bf16x2.f32 %0, %1, %2;" : "=r"(r) : "f"(hi), "f"(lo));
    return r;
}
__device__ __forceinline__ void split2(float v0, float v1, uint32_t& hp, uint32_t& lp) {
    hp = pack_bf2(v0, v1);
    float h0 = __uint_as_float(hp << 16);
    float h1 = __uint_as_float(hp & 0xFFFF0000u);
    lp = pack_bf2(v0 - h0, v1 - h1);
}
__device__ __forceinline__ float join2(uint32_t hp, uint32_t lp, int which) {
    float h = which ? __uint_as_float(hp & 0xFFFF0000u) : __uint_as_float(hp << 16);
    float l = which ? __uint_as_float(lp & 0xFFFF0000u) : __uint_as_float(lp << 16);
    return h + l;
}
__device__ __forceinline__ void ldsm4(uint32_t addr, uint32_t r[4]) {
    asm volatile("ldmatrix.sync.aligned.m8n8.x4.shared.b16 {%0,%1,%2,%3}, [%4];"
        : "=r"(r[0]), "=r"(r[1]), "=r"(r[2]), "=r"(r[3]) : "r"(addr));
}
__device__ __forceinline__ void mma16816(float c[4], const uint32_t a[4],
                                         uint32_t b0, uint32_t b1) {
    asm volatile("mma.sync.aligned.m16n8k16.row.col.f32.bf16.bf16.f32 "
        "{%0,%1,%2,%3}, {%4,%5,%6,%7}, {%8,%9}, {%0,%1,%2,%3};"
        : "+f"(c[0]), "+f"(c[1]), "+f"(c[2]), "+f"(c[3])
        : "r"(a[0]), "r"(a[1]), "r"(a[2]), "r"(a[3]), "r"(b0), "r"(b1));
}
__device__ __forceinline__ void cpasync16(uint32_t dst, const void* src) {
    asm volatile("cp.async.cg.shared.global [%0], [%1], 16;" :: "r"(dst), "l"(src));
}
#define CP_COMMIT() asm volatile("cp.async.commit_group;" ::: "memory")
#define CP_WAIT1()  asm volatile("cp.async.wait_group 1;" ::: "memory")
#define CP_WAIT0()  asm volatile("cp.async.wait_group 0;" ::: "memory")

// TILE64 : [128 rows][64 halves], row 128B, 8x16B chunks, ch ^= row&7
// TILE128: [128 rows][128 halves], row 256B, 16x16B chunks, ch ^= row&7 (low 3 bits)
__device__ __forceinline__ uint32_t a64(uint32_t base, int fr, int ksi,
                                        int rA, int xr, int kq) {
    return base + (uint32_t)((fr + rA) * 128 + (((ksi * 2 + kq) ^ xr) << 4));
}
__device__ __forceinline__ uint32_t a128(uint32_t base, int fr, int ksi,
                                         int rA, int xr, int kq) {
    return base + (uint32_t)((fr + rA) * 256 + (((ksi * 2 + kq) ^ xr) << 4));
}
__device__ __forceinline__ uint32_t SWZ128(int row, int k) {
    return (uint32_t)(row * 256 + ((((k >> 3) ^ (row & 7)) << 4)) + ((k & 7) << 1));
}

// loaders for 1024-thread blocks
__device__ __forceinline__ void ld_t64_1024(uint32_t dst, const unsigned char* src,
                                            int stride, int tid) {
    int row = tid >> 3, ch = tid & 7;
    cpasync16(dst + row * 128 + ((ch ^ (row & 7)) << 4),
              src + (size_t)row * stride + ch * 16);
}
__device__ __forceinline__ void ld_t128_1024(uint32_t dst, const unsigned char* src,
                                             int stride, int tid) {
    #pragma unroll
    for (int i = 0; i < 2; i++) {
        int idx = i * 1024 + tid;
        int row = idx >> 4, ch = idx & 15;
        cpasync16(dst + row * 256 + (((ch ^ (row & 7)) & 15) << 4),
                  src + (size_t)row * stride + ch * 16);
    }
}

// ---------------------------------------------------------------------------
// Prep kernels
// ---------------------------------------------------------------------------
__global__ void qk_split_kernel(const float* __restrict__ q, const float* __restrict__ k) {
    const bool isq = (blockIdx.y == 0);
    const float* src = isq ? q : k;
    unsigned char* hi = isq ? g_qh : g_kh;
    unsigned char* lo = isq ? g_ql : g_kl;
    const float scale = isq ? INV_TEMP : 1.0f;
    size_t i4 = (size_t)blockIdx.x * 256 + threadIdx.x;
    float4 v = ((const float4*)src)[i4];
    v.x *= scale; v.y *= scale; v.z *= scale; v.w *= scale;
    uint32_t hp0, lp0, hp1, lp1;
    split2(v.x, v.y, hp0, lp0);
    split2(v.z, v.w, hp1, lp1);
    ((uint2*)hi)[i4] = make_uint2(hp0, hp1);
    ((uint2*)lo)[i4] = make_uint2(lp0, lp1);
}

__global__ void v_split_T_kernel(const float* __restrict__ v) {
    __shared__ float tile[32][33];
    const int t0 = blockIdx.x * 32;
    const int bh = blockIdx.y;
    const float* src = v + (size_t)bh * TT * DD;
    unsigned char* dh = g_vh + (size_t)bh * DD * TT * 2;
    unsigned char* dl = g_vl + (size_t)bh * DD * TT * 2;
    const int tid = threadIdx.x;
    for (int d0 = 0; d0 < DD; d0 += 32) {
        #pragma unroll
        for (int i = 0; i < 4; i++) {
            int idx = i * 256 + tid;
            int r = idx >> 5, c = idx & 31;
            tile[r][c] = src[(size_t)(t0 + r) * DD + d0 + c];
        }
        __syncthreads();
        #pragma unroll
        for (int i = 0; i < 2; i++) {
            int idx = i * 256 + tid;
            int r = idx >> 4, c2 = (idx & 15) * 2;
            float v0 = tile[c2][r], v1 = tile[c2 + 1][r];
            uint32_t hp, lp;
            split2(v0, v1, hp, lp);
            size_t off = ((size_t)(d0 + r) * TT + t0 + c2) * 2;
            *(uint32_t*)(dh + off) = hp;
            *(uint32_t*)(dl + off) = lp;
        }
        __syncthreads();
    }
}

__global__ void ft_split_T_kernel(const float* __restrict__ af) {
    __shared__ float tile[32][33];
    const int e0 = blockIdx.x * 32;
    const int bh = blockIdx.y;
    const float* src = af + (size_t)bh * DD * DD;
    unsigned char* dh = g_fh + (size_t)bh * DD * DD * 2;
    unsigned char* dl = g_fl + (size_t)bh * DD * DD * 2;
    const int tid = threadIdx.x;
    for (int d0 = 0; d0 < DD; d0 += 32) {
        #pragma unroll
        for (int i = 0; i < 4; i++) {
            int idx = i * 256 + tid;
            int r = idx >> 5, c = idx & 31;
            tile[r][c] = src[(size_t)(d0 + r) * DD + e0 + c];
        }
        __syncthreads();
        #pragma unroll
        for (int i = 0; i < 2; i++) {
            int idx = i * 256 + tid;
            int r = idx >> 4, c2 = (idx & 15) * 2;
            float v0 = tile[c2][r], v1 = tile[c2 + 1][r];
            uint32_t hp, lp;
            split2(v0, v1, hp, lp);
            size_t off = ((size_t)(e0 + r) * DD + d0 + c2) * 2;
            *(uint32_t*)(dh + off) = hp;
            *(uint32_t*)(dl + off) = lp;
        }
        __syncthreads();
    }
}

// ---------------------------------------------------------------------------
// Feature attention (CUDA-core f32x2; not the bottleneck)
// ---------------------------------------------------------------------------
__device__ __forceinline__ u64t pk2(float lo, float hi) {
    u64t r; asm("mov.b64 %0, {%1, %2};" : "=l"(r) : "f"(lo), "f"(hi)); return r;
}
__device__ __forceinline__ void fma2(u64t& d, u64t a, u64t b) {
    asm("fma.rn.f32x2 %0, %1, %2, %0;" : "+l"(d) : "l"(a), "l"(b));
}
__device__ __forceinline__ void up2(u64t v, float& a, float& b) {
    asm("mov.b64 {%0, %1}, %2;" : "=f"(a), "=f"(b) : "l"(v));
}

__global__ void __launch_bounds__(256) feature_attn_kernel(
    const float* __restrict__ qf, const float* __restrict__ kf,
    float* __restrict__ attn_f) {
    __shared__ float qs[32 * 34];
    __shared__ float ks[32 * 132];
    __shared__ float Sf[32 * 132];

    const int bh = blockIdx.y;
    const int d0blk = blockIdx.x * 32;
    const float* q = qf + (size_t)bh * TT * DD;
    const float* k = kf + (size_t)bh * TT * DD;
    const int tid = threadIdx.x;
    const int ty = tid >> 4, tx = tid & 15;
    const int r0 = ty * 2;
    const int e0 = tx * 8;

    u64t acc[2][4];
    #pragma unroll
    for (int i = 0; i < 2; i++)
        #pragma unroll
        for (int j = 0; j < 4; j++) acc[i][j] = 0ull;

    for (int tt = 0; tt < TT; tt += 32) {
        #pragma unroll
        for (int i = 0; i < 4; i++) {
            int idx = i * 256 + tid;
            int r = idx >> 5, c = idx & 31;
            qs[r * 34 + c] = q[(size_t)(tt + r) * DD + d0blk + c] * INV_TEMP;
        }
        #pragma unroll
        for (int i = 0; i < 4; i++) {
            int idx = i * 256 + tid;
            int r = idx >> 5, c4 = (idx & 31) * 4;
            *(float4*)&ks[r * 132 + c4] = *(const float4*)&k[(size_t)(tt + r) * DD + c4];
        }
        __syncthreads();
        #pragma unroll 4
        for (int t = 0; t < 32; t++) {
            float2 a = *(float2*)&qs[t * 34 + r0];
            ulonglong2 b0 = *(ulonglong2*)&ks[t * 132 + e0];
            ulonglong2 b1 = *(ulonglong2*)&ks[t * 132 + e0 + 4];
            u64t a0 = pk2(a.x, a.x), a1 = pk2(a.y, a.y);
            fma2(acc[0][0], a0, b0.x); fma2(acc[0][1], a0, b0.y);
            fma2(acc[0][2], a0, b1.x); fma2(acc[0][3], a0, b1.y);
            fma2(acc[1][0], a1, b0.x); fma2(acc[1][1], a1, b0.y);
            fma2(acc[1][2], a1, b1.x); fma2(acc[1][3], a1, b1.y);
        }
        __syncthreads();
    }

    #pragma unroll
    for (int i = 0; i < 2; i++) {
        float x[8];
        up2(acc[i][0], x[0], x[1]); up2(acc[i][1], x[2], x[3]);
        up2(acc[i][2], x[4], x[5]); up2(acc[i][3], x[6], x[7]);
        *(float4*)&Sf[(r0 + i) * 132 + e0]     = make_float4(x[0], x[1], x[2], x[3]);
        *(float4*)&Sf[(r0 + i) * 132 + e0 + 4] = make_float4(x[4], x[5], x[6], x[7]);
    }
    __syncthreads();

    const int lane = tid & 31, w = tid >> 5;
    float* af = attn_f + (size_t)bh * DD * DD;
    #pragma unroll
    for (int rr = 0; rr < 4; rr++) {
        int r = w * 4 + rr;
        float vv[4], mx = -1e30f;
        #pragma unroll
        for (int kk = 0; kk < 4; kk++) {
            vv[kk] = Sf[r * 132 + lane + 32 * kk];
            mx = fmaxf(mx, vv[kk]);
        }
        #pragma unroll
        for (int o = 16; o; o >>= 1) mx = fmaxf(mx, __shfl_xor_sync(~0u, mx, o));
        float ssum = 0.f;
        #pragma unroll
        for (int kk = 0; kk < 4; kk++) { vv[kk] = __expf(vv[kk] - mx); ssum += vv[kk]; }
        #pragma unroll
        for (int o = 16; o; o >>= 1) ssum += __shfl_xor_sync(~0u, ssum, o);
        float iv = 1.0f / ssum;
        #pragma unroll
        for (int kk = 0; kk < 4; kk++)
            af[(size_t)(d0blk + r) * DD + lane + 32 * kk] = vv[kk] * iv;
    }
}

// ---------------------------------------------------------------------------
// Kernel S: scores via mma.sync, 1024 threads (32 warps, warp grid 8x4,
// warp tile 16 rows x 32 cols).  Writes E hi/lo + g_inv + normalized attn_t.
// smem: Q 4xTILE64 (64K) | B 2 bufs x 4xTILE64 (128K) | red/inv
// ---------------------------------------------------------------------------
#define S_Q   0
#define S_B   65536
#define S_RED 196608
#define S_INV 197120
#define S_SMEM 197632

__global__ void __launch_bounds__(1024, 1) score_mma_kernel(float* __restrict__ attn_t) {
    extern __shared__ char sm[];
    const uint32_t sb = smem_u32(sm);
    float* red  = (float*)(sm + S_RED);
    float* invs = (float*)(sm + S_INV);

    const int bh = blockIdx.y;
    const int r0 = blockIdx.x * 128;
    const int tid = threadIdx.x;
    const int wid = tid >> 5, lane = tid & 31;
    const int s_wm = wid & 7, s_wn = wid >> 3;
    const int g = lane >> 2, tig = lane & 3;
    const int rA = (lane & 7) + ((lane >> 3) & 1) * 8;
    const int xr = rA & 7, kq = lane >> 4;

    if (tid < 128) red[tid] = 0.f;

    const unsigned char* qh = g_qh + ((size_t)bh * TT + r0) * 256;
    const unsigned char* ql = g_ql + ((size_t)bh * TT + r0) * 256;
    const unsigned char* kh = g_kh + (size_t)bh * TT * 256;
    const unsigned char* kl = g_kl + (size_t)bh * TT * 256;
    unsigned char* ehb = g_eh + ((size_t)bh * TT + r0) * 2048;
    unsigned char* elb = g_el + ((size_t)bh * TT + r0) * 2048;

    // prologue: Q resident + K chunk 0 (group 0), K chunk 1 (group 1)
    ld_t64_1024(sb + S_Q +     0, qh,       256, tid);
    ld_t64_1024(sb + S_Q + 16384, qh + 128, 256, tid);
    ld_t64_1024(sb + S_Q + 32768, ql,       256, tid);
    ld_t64_1024(sb + S_Q + 49152, ql + 128, 256, tid);
    ld_t64_1024(sb + S_B +     0, kh,       256, tid);
    ld_t64_1024(sb + S_B + 16384, kh + 128, 256, tid);
    ld_t64_1024(sb + S_B + 32768, kl,       256, tid);
    ld_t64_1024(sb + S_B + 49152, kl + 128, 256, tid);
    CP_COMMIT();

    float rsum[2] = {0, 0};
    const int fr = s_wm * 16;

    for (int c = 0; c < 8; c++) {
        if (c < 7) {
            const unsigned char* kh1 = kh + (size_t)(c + 1) * 128 * 256;
            const unsigned char* kl1 = kl + (size_t)(c + 1) * 128 * 256;
            uint32_t bb = sb + S_B + ((c + 1) & 1) * 65536;
            ld_t64_1024(bb +     0, kh1,       256, tid);
            ld_t64_1024(bb + 16384, kh1 + 128, 256, tid);
            ld_t64_1024(bb + 32768, kl1,       256, tid);
            ld_t64_1024(bb + 49152, kl1 + 128, 256, tid);
            CP_COMMIT();
            CP_WAIT1();
        } else {
            CP_WAIT0();
        }
        __syncthreads();

        const uint32_t qb = sb + S_Q;
        const uint32_t bb = sb + S_B + (c & 1) * 65536;
        float acc[4][4];
        #pragma unroll
        for (int j = 0; j < 4; j++)
            #pragma unroll
            for (int i = 0; i < 4; i++) acc[j][i] = 0.f;

        #pragma unroll
        for (int kt = 0; kt < 2; kt++) {
            #pragma unroll
            for (int ksi = 0; ksi < 4; ksi++) {
                uint32_t ah[4], al[4], b0h[4], b1h[4], b0l[4], b1l[4];
                ldsm4(a64(qb + kt * 16384, fr, ksi, rA, xr, kq), ah);
                ldsm4(a64(qb + 32768 + kt * 16384, fr, ksi, rA, xr, kq), al);
                {
                    int nr = s_wn * 32;
                    ldsm4(a64(bb + kt * 16384, nr, ksi, rA, xr, kq), b0h);
                    ldsm4(a64(bb + kt * 16384, nr + 16, ksi, rA, xr, kq), b1h);
                    ldsm4(a64(bb + 32768 + kt * 16384, nr, ksi, rA, xr, kq), b0l);
                    ldsm4(a64(bb + 32768 + kt * 16384, nr + 16, ksi, rA, xr, kq), b1l);
                }
                mma16816(acc[0], ah, b0h[0], b0h[2]);
                mma16816(acc[1], ah, b0h[1], b0h[3]);
                mma16816(acc[2], ah, b1h[0], b1h[2]);
                mma16816(acc[3], ah, b1h[1], b1h[3]);
                mma16816(acc[0], ah, b0l[0], b0l[2]);
                mma16816(acc[1], ah, b0l[1], b0l[3]);
                mma16816(acc[2], ah, b1l[0], b1l[2]);
                mma16816(acc[3], ah, b1l[1], b1l[3]);
                mma16816(acc[0], al, b0h[0], b0h[2]);
                mma16816(acc[1], al, b0h[1], b0h[3]);
                mma16816(acc[2], al, b1h[0], b1h[2]);
                mma16816(acc[3], al, b1h[1], b1h[3]);
            }
        }

        // epilogue: exp, rowsum, store split E
        const int row = fr + g;
        #pragma unroll
        for (int j = 0; j < 4; j++) {
            float e0 = __expf(acc[j][0]);
            float e1 = __expf(acc[j][1]);
            float e2 = __expf(acc[j][2]);
            float e3 = __expf(acc[j][3]);
            rsum[0] += e0 + e1;
            rsum[1] += e2 + e3;
            int col = c * 128 + s_wn * 32 + j * 8 + tig * 2;
            uint32_t hp, lp;
            split2(e0, e1, hp, lp);
            *(uint32_t*)(ehb + (size_t)row * 2048 + col * 2) = hp;
            *(uint32_t*)(elb + (size_t)row * 2048 + col * 2) = lp;
            split2(e2, e3, hp, lp);
            *(uint32_t*)(ehb + (size_t)(row + 8) * 2048 + col * 2) = hp;
            *(uint32_t*)(elb + (size_t)(row + 8) * 2048 + col * 2) = lp;
        }
        __syncthreads();
    }

    // rowsum reduce + inverses
    rsum[0] += __shfl_xor_sync(~0u, rsum[0], 1);
    rsum[0] += __shfl_xor_sync(~0u, rsum[0], 2);
    rsum[1] += __shfl_xor_sync(~0u, rsum[1], 1);
    rsum[1] += __shfl_xor_sync(~0u, rsum[1], 2);
    if (tig == 0) {
        atomicAdd(&red[fr + g],     rsum[0]);
        atomicAdd(&red[fr + g + 8], rsum[1]);
    }
    __syncthreads();
    if (tid < 128) {
        float iv = 1.0f / red[tid];
        invs[tid] = iv;
        g_inv[bh * TT + r0 + tid] = iv;
    }
    __syncthreads();

    // normalize: read E hi/lo (L2-hot), write attn_time f32
    float* at = attn_t + ((size_t)bh * TT + r0) * TT;
    #pragma unroll 4
    for (int it = 0; it < 16; it++) {
        int idx = it * 1024 + tid;
        int row = idx >> 7;
        int cb = (idx & 127) * 8;
        float iv = invs[row];
        uint4 hv = *(const uint4*)(ehb + (size_t)row * 2048 + cb * 2);
        uint4 lv = *(const uint4*)(elb + (size_t)row * 2048 + cb * 2);
        float o[8];
        o[0] = join2(hv.x, lv.x, 0) * iv; o[1] = join2(hv.x, lv.x, 1) * iv;
        o[2] = join2(hv.y, lv.y, 0) * iv; o[3] = join2(hv.y, lv.y, 1) * iv;
        o[4] = join2(hv.z, lv.z, 0) * iv; o[5] = join2(hv.z, lv.z, 1) * iv;
        o[6] = join2(hv.w, lv.w, 0) * iv; o[7] = join2(hv.w, lv.w, 1) * iv;
        *(float4*)&at[(size_t)row * TT + cb]     = make_float4(o[0], o[1], o[2], o[3]);
        *(float4*)&at[(size_t)row * TT + cb + 4] = make_float4(o[4], o[5], o[6], o[7]);
    }
}

// ---------------------------------------------------------------------------
// Kernel T: tv = E @ V (16 s-chunks of 64, double-buffered), then
// out = diag(inv) * tv @ F^T.  1024 threads, warp grid 8x4 (16r x 32c tiles).
// smem: A 2 bufs x (EH 16K + EL 16K) | B 2 bufs x (VH 16K + VL 16K)
// ---------------------------------------------------------------------------
#define T_A 0
#define T_B 65536
#define T_SMEM 131072

__global__ void __launch_bounds__(1024, 1) tv_out_mma_kernel(float* __restrict__ out) {
    extern __shared__ char sm[];
    const uint32_t sb = smem_u32(sm);

    const int bh = blockIdx.y;
    const int r0 = blockIdx.x * 128;
    const int tid = threadIdx.x;
    const int wid = tid >> 5, lane = tid & 31;
    const int t_wm = wid & 7, t_wn = wid >> 3;
    const int g = lane >> 2, tig = lane & 3;
    const int rA = (lane & 7) + ((lane >> 3) & 1) * 8;
    const int xr = rA & 7, kq = lane >> 4;
    const int fr = t_wm * 16;

    const unsigned char* ehb = g_eh + ((size_t)bh * TT + r0) * 2048;
    const unsigned char* elb = g_el + ((size_t)bh * TT + r0) * 2048;
    const unsigned char* vhb = g_vh + (size_t)bh * DD * 2048;
    const unsigned char* vlb = g_vl + (size_t)bh * DD * 2048;

    // prologue: chunk 0
    ld_t64_1024(sb + T_A +     0, ehb, 2048, tid);
    ld_t64_1024(sb + T_A + 16384, elb, 2048, tid);
    ld_t64_1024(sb + T_B +     0, vhb, 2048, tid);
    ld_t64_1024(sb + T_B + 16384, vlb, 2048, tid);
    CP_COMMIT();

    float acc2[4][4];
    #pragma unroll
    for (int j = 0; j < 4; j++)
        #pragma unroll
        for (int i = 0; i < 4; i++) acc2[j][i] = 0.f;

    for (int c = 0; c < 16; c++) {
        if (c < 15) {
            int off = (c + 1) * 128;
            uint32_t ab = sb + T_A + ((c + 1) & 1) * 32768;
            uint32_t bb = sb + T_B + ((c + 1) & 1) * 32768;
            ld_t64_1024(ab,         ehb + off, 2048, tid);
            ld_t64_1024(ab + 16384, elb + off, 2048, tid);
            ld_t64_1024(bb,         vhb + off, 2048, tid);
            ld_t64_1024(bb + 16384, vlb + off, 2048, tid);
            CP_COMMIT();
            CP_WAIT1();
        } else {
            CP_WAIT0();
        }
        __syncthreads();

        const uint32_t ab = sb + T_A + (c & 1) * 32768;
        const uint32_t bb = sb + T_B + (c & 1) * 32768;
        #pragma unroll
        for (int ksi = 0; ksi < 4; ksi++) {
            uint32_t ah[4], al[4], b0h[4], b1h[4], b0l[4], b1l[4];
            ldsm4(a64(ab, fr, ksi, rA, xr, kq), ah);
            ldsm4(a64(ab + 16384, fr, ksi, rA, xr, kq), al);
            {
                int nr = t_wn * 32;
                ldsm4(a64(bb, nr, ksi, rA, xr, kq), b0h);
                ldsm4(a64(bb, nr + 16, ksi, rA, xr, kq), b1h);
                ldsm4(a64(bb + 16384, nr, ksi, rA, xr, kq), b0l);
                ldsm4(a64(bb + 16384, nr + 16, ksi, rA, xr, kq), b1l);
            }
            mma16816(acc2[0], ah, b0h[0], b0h[2]);
            mma16816(acc2[1], ah, b0h[1], b0h[3]);
            mma16816(acc2[2], ah, b1h[0], b1h[2]);
            mma16816(acc2[3], ah, b1h[1], b1h[3]);
            mma16816(acc2[0], ah, b0l[0], b0l[2]);
            mma16816(acc2[1], ah, b0l[1], b0l[3]);
            mma16816(acc2[2], ah, b1l[0], b1l[2]);
            mma16816(acc2[3], ah, b1l[1], b1l[3]);
            mma16816(acc2[0], al, b0h[0], b0h[2]);
            mma16816(acc2[1], al, b0h[1], b0h[3]);
            mma16816(acc2[2], al, b1h[0], b1h[2]);
            mma16816(acc2[3], al, b1h[1], b1h[3]);
        }
        __syncthreads();
    }

    // F^T loads into B region (TILE128 hi at T_B, lo at T_B+32768)
    {
        const unsigned char* fhb = g_fh + (size_t)bh * DD * 256;
        const unsigned char* flb = g_fl + (size_t)bh * DD * 256;
        ld_t128_1024(sb + T_B,         fhb, 256, tid);
        ld_t128_1024(sb + T_B + 32768, flb, 256, tid);
        CP_COMMIT();
    }
    // stage tv split into A region (TILE128 hi at T_A, lo at T_A+32768)
    {
        const int row = fr + g;
        #pragma unroll
        for (int j = 0; j < 4; j++) {
            int d0v = t_wn * 32 + j * 8 + tig * 2;
            uint32_t hp, lp;
            split2(acc2[j][0], acc2[j][1], hp, lp);
            *(uint32_t*)(sm + T_A + SWZ128(row, d0v)) = hp;
            *(uint32_t*)(sm + T_A + 32768 + SWZ128(row, d0v)) = lp;
            split2(acc2[j][2], acc2[j][3], hp, lp);
            *(uint32_t*)(sm + T_A + SWZ128(row + 8, d0v)) = hp;
            *(uint32_t*)(sm + T_A + 32768 + SWZ128(row + 8, d0v)) = lp;
        }
    }
    CP_WAIT0();
    __syncthreads();

    // GEMM3: out = tv @ F^T (K = 128, 8 ksi on TILE128)
    float acc3[4][4];
    #pragma unroll
    for (int j = 0; j < 4; j++)
        #pragma unroll
        for (int i = 0; i < 4; i++) acc3[j][i] = 0.f;

    #pragma unroll
    for (int ksi = 0; ksi < 8; ksi++) {
        uint32_t ah[4], al[4], b0h[4], b1h[4], b0l[4], b1l[4];
        ldsm4(a128(sb + T_A, fr, ksi, rA, xr, kq), ah);
        ldsm4(a128(sb + T_A + 32768, fr, ksi, rA, xr, kq), al);
        {
            int nr = t_wn * 32;
            ldsm4(a128(sb + T_B, nr, ksi, rA, xr, kq), b0h);
            ldsm4(a128(sb + T_B, nr + 16, ksi, rA, xr, kq), b1h);
            ldsm4(a128(sb + T_B + 32768, nr, ksi, rA, xr, kq), b0l);
            ldsm4(a128(sb + T_B + 32768, nr + 16, ksi, rA, xr, kq), b1l);
        }
        mma16816(acc3[0], ah, b0h[0], b0h[2]);
        mma16816(acc3[1], ah, b0h[1], b0h[3]);
        mma16816(acc3[2], ah, b1h[0], b1h[2]);
        mma16816(acc3[3], ah, b1h[1], b1h[3]);
        mma16816(acc3[0], ah, b0l[0], b0l[2]);
        mma16816(acc3[1], ah, b0l[1], b0l[3]);
        mma16816(acc3[2], ah, b1l[0], b1l[2]);
        mma16816(acc3[3], ah, b1l[1], b1l[3]);
        mma16816(acc3[0], al, b0h[0], b0h[2]);
        mma16816(acc3[1], al, b0h[1], b0h[3]);
        mma16816(acc3[2], al, b1h[0], b1h[2]);
        mma16816(acc3[3], al, b1h[1], b1h[3]);
    }

    const float* ginv = g_inv + bh * TT + r0;
    float* op = out + ((size_t)bh * TT + r0) * DD;
    {
        const int row = fr + g;
        float iva = ginv[row];
        float ivb = ginv[row + 8];
        #pragma unroll
        for (int j = 0; j < 4; j++) {
            int e = t_wn * 32 + j * 8 + tig * 2;
            *(float2*)&op[(size_t)row * DD + e] =
                make_float2(acc3[j][0] * iva, acc3[j][1] * iva);
            *(float2*)&op[(size_t)(row + 8) * DD + e] =
                make_float2(acc3[j][2] * ivb, acc3[j][3] * ivb);
        }
    }
}

// ---------------------------------------------------------------------------
// Launch
// ---------------------------------------------------------------------------
extern "C" void kernel_launch(void* const* d_in, const int* in_sizes, int n_in,
                              void* d_out, int out_size) {
    const float* q_time    = (const float*)d_in[0];
    const float* k_time    = (const float*)d_in[1];
    const float* q_feature = (const float*)d_in[2];
    const float* k_feature = (const float*)d_in[3];
    const float* v         = (const float*)d_in[4];

    float* out    = (float*)d_out;                       // [BH][T][D]
    float* attn_t = out + (size_t)BHN * TT * DD;         // [BH][T][T]
    float* attn_f = attn_t + (size_t)BHN * TT * TT;      // [BH][D][D]

    cudaFuncSetAttribute(score_mma_kernel,
                         cudaFuncAttributeMaxDynamicSharedMemorySize, S_SMEM);
    cudaFuncSetAttribute(tv_out_mma_kernel,
                         cudaFuncAttributeMaxDynamicSharedMemorySize, T_SMEM);

    qk_split_kernel<<<dim3(8192, 2), 256>>>(q_time, k_time);
    v_split_T_kernel<<<dim3(32, BHN), 256>>>(v);
    feature_attn_kernel<<<dim3(4, BHN), 256>>>(q_feature, k_feature, attn_f);
    ft_split_T_kernel<<<dim3(4, BHN), 256>>>(attn_f);
    score_mma_kernel<<<dim3(8, BHN), 1024, S_SMEM>>>(attn_t);
    tv_out_mma_kernel<<<dim3(8, BHN), 1024, T_SMEM>>>(out);
}